// round 9
// baseline (speedup 1.0000x reference)
#include <cuda_runtime.h>
#include <cstdint>

// RoIPooling (TF2 crop_and_resize bilinear, POOL=7)
// feature_map: (1, 256, 256, 512) float32 NHWC
// proposals:   (512, 4) int32  [x, y, w, h]
// output:      (512, 7, 7, 512) float32
//
// R7: kernel sits ON the chip LTS cap (256MB L2 traffic @ ~11.9TB/s =
// 21.5us ncu). Only lever left: fewer L2 bytes. R6's cp.async staging makes
// corner elision safe: skipping a redundant corner = not issuing its cp16
// (uniform branch, no register chains — the R4 trap), and the consumer
// redirects through a SMEM SLOT INDEX select (address math + LDS, off the
// L2 path). Elided corners: fx==0 / fy==0 (zero weight) and ix1==ix0 /
// iy1==iy0 (clamp duplicates). Substitutions are bit-identical.

#define POOL 7
#define FM_W 256
#define FM_C 512
#define NPROP 512
#define C4 (FM_C / 4)
#define DEPTH 4

__device__ __forceinline__ void cp16(uint32_t dst_smem, const void* src) {
    asm volatile("cp.async.cg.shared.global [%0], [%1], 16;\n"
                 :: "r"(dst_smem), "l"(src) : "memory");
}
__device__ __forceinline__ void cp_commit() {
    asm volatile("cp.async.commit_group;\n" ::: "memory");
}
template <int N>
__device__ __forceinline__ void cp_wait() {
    asm volatile("cp.async.wait_group %0;\n" :: "n"(N) : "memory");
}

struct Ctx {
    const float4* row0;
    const float4* row1;
    float4*       orow;
    float wf, xscale, fy, ofy;
    int   bw, c;
    bool  need_y1;     // row1 is a distinct, nonzero-weight row
    uint32_t sbase;    // smem base address (bytes)
};

// x coords for cell px (bit-identical to reference float32 math)
__device__ __forceinline__ void xcoords(const Ctx& k, int px,
                                        int& ix0, int& ix1, float& fx,
                                        bool& need_x1) {
    float sx = ((float)px + 0.5f) * k.xscale - 0.5f;
    sx = fminf(fmaxf(sx, 0.0f), k.wf - 1.0f);
    ix0 = (int)floorf(sx);
    ix1 = min(ix0 + 1, k.bw - 1);
    fx  = sx - (float)ix0;
    need_x1 = (ix1 != ix0) && (fx != 0.0f);
}

// stage slot layout: slot s, corner j, thread t at sbase + ((s*4+j)*128 + t)*16
__device__ __forceinline__ uint32_t slot_addr(const Ctx& k, int s, int j) {
    return k.sbase + (uint32_t)(((s * 4 + j) * 128 + k.c) * 16);
}

__device__ __forceinline__ void issue(const Ctx& k, int px) {
    int ix0, ix1; float fx; bool nx;
    xcoords(k, px, ix0, ix1, fx, nx);
    const int s = px & (DEPTH - 1);
    // corner 0 always needed
    cp16(slot_addr(k, s, 0), &k.row0[ix0 * C4 + k.c]);
    // remaining corners only when they contribute distinct bytes
    if (nx)              cp16(slot_addr(k, s, 1), &k.row0[ix1 * C4 + k.c]);
    if (k.need_y1)       cp16(slot_addr(k, s, 2), &k.row1[ix0 * C4 + k.c]);
    if (nx && k.need_y1) cp16(slot_addr(k, s, 3), &k.row1[ix1 * C4 + k.c]);
    cp_commit();
}

template <int WC>
__device__ __forceinline__ void consume(const Ctx& k, const float4* buf, int px) {
    int ix0, ix1; float fx; bool nx;
    xcoords(k, px, ix0, ix1, fx, nx);      // recompute (cheap ALU)
    const float of = 1.0f - fx;
    const int s = px & (DEPTH - 1);

    // slot remap: elided corners read the staged duplicate (bit-identical)
    const int jb = nx ? 1 : 0;
    const int jg = k.need_y1 ? 2 : 0;
    const int jd = k.need_y1 ? (nx ? 3 : 2) : jb;

    cp_wait<WC>();                          // stage px's group retired

    const float4 a = buf[(s * 4 + 0)  * 128 + k.c];
    const float4 b = buf[(s * 4 + jb) * 128 + k.c];
    const float4 g = buf[(s * 4 + jg) * 128 + k.c];
    const float4 d = buf[(s * 4 + jd) * 128 + k.c];

    float4 o;
    o.x = (a.x * of + b.x * fx) * k.ofy + (g.x * of + d.x * fx) * k.fy;
    o.y = (a.y * of + b.y * fx) * k.ofy + (g.y * of + d.y * fx) * k.fy;
    o.z = (a.z * of + b.z * fx) * k.ofy + (g.z * of + d.z * fx) * k.fy;
    o.w = (a.w * of + b.w * fx) * k.ofy + (g.w * of + d.w * fx) * k.fy;

    __stcs(&k.orow[px * C4 + k.c], o);
}

__global__ __launch_bounds__(128)
void roi_pool_kernel(const float* __restrict__ fm,
                     const int*   __restrict__ props,
                     float*       __restrict__ out)
{
    __shared__ float4 buf[DEPTH * 4 * 128];    // 32 KB

    const int bid = blockIdx.x;                // 0 .. 3583
    const int n   = bid / POOL;
    const int py  = bid - n * POOL;

    const int4 box = reinterpret_cast<const int4*>(props)[n];
    const int bx = box.x, by = box.y, bw = box.z, bh = box.w;

    // --- y axis coords ---
    const float hf = (float)bh;
    float sy = ((float)py + 0.5f) * (hf / (float)POOL) - 0.5f;
    sy = fminf(fmaxf(sy, 0.0f), hf - 1.0f);
    const int   iy0 = (int)floorf(sy);
    const int   iy1 = min(iy0 + 1, bh - 1);

    Ctx k;
    k.fy  = sy - (float)iy0;
    k.ofy = 1.0f - k.fy;
    k.need_y1 = (iy1 != iy0) && (k.fy != 0.0f);
    k.row0 = reinterpret_cast<const float4*>(fm + ((size_t)(by + iy0) * FM_W + bx) * FM_C);
    k.row1 = reinterpret_cast<const float4*>(fm + ((size_t)(by + iy1) * FM_W + bx) * FM_C);
    k.orow = reinterpret_cast<float4*>(out + ((size_t)n * (POOL * POOL) + (size_t)py * POOL) * FM_C);
    k.c   = threadIdx.x;
    k.bw  = bw;
    k.wf  = (float)bw;
    k.xscale = k.wf / (float)POOL;
    {
        uint32_t a;
        asm("{ .reg .u64 t; cvta.to.shared.u64 t, %1; cvt.u32.u64 %0, t; }"
            : "=r"(a) : "l"((const void*)buf));
        k.sbase = a;
    }

    // prologue: fill the pipe (4 stages in flight)
    issue(k, 0); issue(k, 1); issue(k, 2); issue(k, 3);

    // steady state + drain; wait counts keep exactly stage-px retired
    consume<3>(k, buf, 0); issue(k, 4);
    consume<3>(k, buf, 1); issue(k, 5);
    consume<3>(k, buf, 2); issue(k, 6);
    consume<3>(k, buf, 3);
    consume<2>(k, buf, 4);
    consume<1>(k, buf, 5);
    consume<0>(k, buf, 6);
}

extern "C" void kernel_launch(void* const* d_in, const int* in_sizes, int n_in,
                              void* d_out, int out_size)
{
    const float* fm    = (const float*)d_in[0];
    const int*   props = (const int*)d_in[1];
    float*       out   = (float*)d_out;

    const int blocks = NPROP * POOL;      // 3584
    roi_pool_kernel<<<blocks, 128>>>(fm, props, out);
}